// round 5
// baseline (speedup 1.0000x reference)
#include <cuda_runtime.h>

// TransD: out = h - t + r + rp * ((hp.h) - (tp.t)),  B=262144, D=128.
// Pipeline: bucket-sort row ids by head>>8 (4096 buckets) so repeated heads
// are processed adjacently -> head-gather repeats become L2 hits, and head
// gathers get DRAM page locality. Main kernel: 1 warp per row via perm[].

static constexpr int DV4   = 32;      // 128 floats / 4
static constexpr int MAXB  = 262144;
static constexpr int NBUCK = 4096;
static constexpr int SHIFT = 8;       // NUM_ENTS=1e6 -> max bucket 3906 < 4096

__device__ int g_cnt[NBUCK];
__device__ int g_perm[MAXB];

__global__ void k_zero() {
    int i = blockIdx.x * blockDim.x + threadIdx.x;
    if (i < NBUCK) g_cnt[i] = 0;
}

__global__ void k_hist(const int* __restrict__ head, int B) {
    int i = blockIdx.x * blockDim.x + threadIdx.x;
    if (i < B) atomicAdd(&g_cnt[head[i] >> SHIFT], 1);
}

// Single block, 1024 threads: exclusive scan of g_cnt[4096] in place.
__global__ __launch_bounds__(1024) void k_scan() {
    __shared__ int s[NBUCK];
    __shared__ int ts[1024];
    int t = threadIdx.x;
    for (int i = t; i < NBUCK; i += 1024) s[i] = g_cnt[i];
    __syncthreads();
    int v0 = s[t*4], v1 = s[t*4+1], v2 = s[t*4+2], v3 = s[t*4+3];
    int sum = v0 + v1 + v2 + v3;
    ts[t] = sum;
    __syncthreads();
    for (int o = 1; o < 1024; o <<= 1) {
        int x = (t >= o) ? ts[t - o] : 0;
        __syncthreads();
        if (t >= o) ts[t] += x;
        __syncthreads();
    }
    int excl = ts[t] - sum;              // exclusive prefix of this thread's chunk
    s[t*4]   = excl;
    s[t*4+1] = excl + v0;
    s[t*4+2] = excl + v0 + v1;
    s[t*4+3] = excl + v0 + v1 + v2;
    __syncthreads();
    for (int i = t; i < NBUCK; i += 1024) g_cnt[i] = s[i];
}

__global__ void k_scatter(const int* __restrict__ head, int B) {
    int i = blockIdx.x * blockDim.x + threadIdx.x;
    if (i < B) {
        int b = head[i] >> SHIFT;
        int p = atomicAdd(&g_cnt[b], 1);
        g_perm[p] = i;
    }
}

__device__ __forceinline__ float4 ldg_evl(const float4* p, unsigned long long pol) {
    float4 v;
    asm volatile("ld.global.nc.L2::cache_hint.v4.f32 {%0,%1,%2,%3}, [%4], %5;"
                 : "=f"(v.x), "=f"(v.y), "=f"(v.z), "=f"(v.w)
                 : "l"(p), "l"(pol));
    return v;
}

template <bool PERMUTED>
__global__ __launch_bounds__(256) void transd_kernel(
    const int* __restrict__ head,
    const int* __restrict__ relation,
    const int* __restrict__ tail,
    const float4* __restrict__ ent_emb,
    const float4* __restrict__ ent_map_emb,
    const float4* __restrict__ rel_emb,
    const float4* __restrict__ rel_map_emb,
    float4* __restrict__ out,
    int B)
{
    int gtid = blockIdx.x * blockDim.x + threadIdx.x;
    int wid  = gtid >> 5;
    int lane = gtid & 31;
    if (wid >= B) return;

    int row = PERMUTED ? __ldg(&g_perm[wid]) : wid;

    unsigned long long pol;
    asm volatile("createpolicy.fractional.L2::evict_last.b64 %0, 1.0;" : "=l"(pol));

    int hi = __ldg(&head[row]);
    int ri = __ldg(&relation[row]);
    int ti = __ldg(&tail[row]);

    long hoff = (long)hi * DV4 + lane;
    long toff = (long)ti * DV4 + lane;
    long roff = (long)ri * DV4 + lane;

    // Front-batch all 6 independent gathers for MLP.
    float4 hv = ldg_evl(&ent_emb[hoff], pol);
    float4 hp = ldg_evl(&ent_map_emb[hoff], pol);
    float4 tv = ldg_evl(&ent_emb[toff], pol);
    float4 tp = ldg_evl(&ent_map_emb[toff], pol);
    float4 rv = __ldg(&rel_emb[roff]);
    float4 rp = __ldg(&rel_map_emb[roff]);

    float sh = hv.x * hp.x + hv.y * hp.y + hv.z * hp.z + hv.w * hp.w;
    float st = tv.x * tp.x + tv.y * tp.y + tv.z * tp.z + tv.w * tp.w;
    float s = sh - st;

    #pragma unroll
    for (int o = 16; o > 0; o >>= 1) {
        s += __shfl_xor_sync(0xffffffffu, s, o);
    }

    float4 o4;
    o4.x = hv.x - tv.x + rv.x + rp.x * s;
    o4.y = hv.y - tv.y + rv.y + rp.y * s;
    o4.z = hv.z - tv.z + rv.z + rp.z * s;
    o4.w = hv.w - tv.w + rv.w + rp.w * s;

    __stcs(&out[(long)row * DV4 + lane], o4);
}

extern "C" void kernel_launch(void* const* d_in, const int* in_sizes, int n_in,
                              void* d_out, int out_size)
{
    const int*    head    = (const int*)d_in[0];
    const int*    rel     = (const int*)d_in[1];
    const int*    tail    = (const int*)d_in[2];
    const float4* ent     = (const float4*)d_in[3];
    const float4* ent_map = (const float4*)d_in[4];
    const float4* rel_e   = (const float4*)d_in[5];
    const float4* rel_map = (const float4*)d_in[6];
    float4*       out     = (float4*)d_out;

    int B = in_sizes[0];
    int blocks = (B + 7) / 8;   // 8 warps (rows) per 256-thread block

    if (B <= MAXB) {
        k_zero<<<(NBUCK + 255) / 256, 256>>>();
        k_hist<<<(B + 255) / 256, 256>>>(head, B);
        k_scan<<<1, 1024>>>();
        k_scatter<<<(B + 255) / 256, 256>>>(head, B);
        transd_kernel<true><<<blocks, 256>>>(head, rel, tail, ent, ent_map,
                                             rel_e, rel_map, out, B);
    } else {
        transd_kernel<false><<<blocks, 256>>>(head, rel, tail, ent, ent_map,
                                              rel_e, rel_map, out, B);
    }
}

// round 6
// speedup vs baseline: 1.2274x; 1.2274x over previous
#include <cuda_runtime.h>

// TransD scoring: out = h - t + r + rp * ((hp.h) - (tp.t))
// One warp per row; lane i handles one float4 (D=128, D/4=32 == warp width).
// Roofline-bound kernel (~620MB DRAM traffic @ ~6.45 TB/s).
//  - entity gathers: evict_last L2 policy (protect the few in-window repeats)
//  - relation loads: deferred past the dot-product (always L2-hit, latency
//    hidden by the shuffle reduction) -> front LDG batch is 4, not 6,
//    reducing L1tex queue depth / cross-CTA spread.
//  - output: streaming store (.cs), don't let 128MB of writes claim L2.

static constexpr int DV4 = 32;  // 128 floats / 4

__device__ __forceinline__ float4 ldg_evl(const float4* p, unsigned long long pol) {
    float4 v;
    asm volatile("ld.global.nc.L2::cache_hint.v4.f32 {%0,%1,%2,%3}, [%4], %5;"
                 : "=f"(v.x), "=f"(v.y), "=f"(v.z), "=f"(v.w)
                 : "l"(p), "l"(pol));
    return v;
}

__global__ __launch_bounds__(256) void transd_kernel(
    const int* __restrict__ head,
    const int* __restrict__ relation,
    const int* __restrict__ tail,
    const float4* __restrict__ ent_emb,
    const float4* __restrict__ ent_map_emb,
    const float4* __restrict__ rel_emb,
    const float4* __restrict__ rel_map_emb,
    float4* __restrict__ out,
    int B)
{
    int gtid = blockIdx.x * blockDim.x + threadIdx.x;
    int row  = gtid >> 5;
    int lane = gtid & 31;
    if (row >= B) return;

    unsigned long long pol;
    asm volatile("createpolicy.fractional.L2::evict_last.b64 %0, 1.0;" : "=l"(pol));

    // Index loads: broadcast within warp.
    int hi = __ldg(&head[row]);
    int ri = __ldg(&relation[row]);
    int ti = __ldg(&tail[row]);

    long hoff = (long)hi * DV4 + lane;
    long toff = (long)ti * DV4 + lane;
    long roff = (long)ri * DV4 + lane;

    // Front-batch the 4 DRAM gathers only.
    float4 hv = ldg_evl(&ent_emb[hoff], pol);
    float4 hp = ldg_evl(&ent_map_emb[hoff], pol);
    float4 tv = ldg_evl(&ent_emb[toff], pol);
    float4 tp = ldg_evl(&ent_map_emb[toff], pol);

    // Per-lane partial dot products; combine before reduction.
    float sh = hv.x * hp.x + hv.y * hp.y + hv.z * hp.z + hv.w * hp.w;
    float st = tv.x * tp.x + tv.y * tp.y + tv.z * tp.z + tv.w * tp.w;
    float s = sh - st;

    // Relation rows live in L2 (512KB tables): issue now, latency hidden
    // by the shuffle butterfly below.
    float4 rv = __ldg(&rel_emb[roff]);
    float4 rp = __ldg(&rel_map_emb[roff]);

    #pragma unroll
    for (int o = 16; o > 0; o >>= 1) {
        s += __shfl_xor_sync(0xffffffffu, s, o);
    }

    float4 o4;
    o4.x = hv.x - tv.x + rv.x + rp.x * s;
    o4.y = hv.y - tv.y + rv.y + rp.y * s;
    o4.z = hv.z - tv.z + rv.z + rp.z * s;
    o4.w = hv.w - tv.w + rv.w + rp.w * s;

    __stcs(&out[(long)row * DV4 + lane], o4);
}

extern "C" void kernel_launch(void* const* d_in, const int* in_sizes, int n_in,
                              void* d_out, int out_size)
{
    const int*    head    = (const int*)d_in[0];
    const int*    rel     = (const int*)d_in[1];
    const int*    tail    = (const int*)d_in[2];
    const float4* ent     = (const float4*)d_in[3];
    const float4* ent_map = (const float4*)d_in[4];
    const float4* rel_e   = (const float4*)d_in[5];
    const float4* rel_map = (const float4*)d_in[6];
    float4*       out     = (float4*)d_out;

    int B = in_sizes[0];
    int blocks = (B + 7) / 8;   // 8 warps (rows) per 256-thread block
    transd_kernel<<<blocks, 256>>>(head, rel, tail, ent, ent_map, rel_e, rel_map, out, B);
}

// round 7
// speedup vs baseline: 1.2278x; 1.0003x over previous
#include <cuda_runtime.h>

// TransD scoring: out = h - t + r + rp * ((hp.h) - (tp.t))
// One warp per row; lane i handles one float4 (D=128, D/4=32 == warp width).
// Roofline-bound (~620MB traffic @ ~6.4TB/s). This round's single change:
// output stores are write-through (st.global.wt) so the 128MB write stream
// never allocates L2 lines -> full L2 capacity serves entity-gather reuse
// (entity loads carry an evict_last policy).

static constexpr int DV4 = 32;  // 128 floats / 4

__device__ __forceinline__ float4 ldg_evl(const float4* p, unsigned long long pol) {
    float4 v;
    asm volatile("ld.global.nc.L2::cache_hint.v4.f32 {%0,%1,%2,%3}, [%4], %5;"
                 : "=f"(v.x), "=f"(v.y), "=f"(v.z), "=f"(v.w)
                 : "l"(p), "l"(pol));
    return v;
}

__global__ __launch_bounds__(256) void transd_kernel(
    const int* __restrict__ head,
    const int* __restrict__ relation,
    const int* __restrict__ tail,
    const float4* __restrict__ ent_emb,
    const float4* __restrict__ ent_map_emb,
    const float4* __restrict__ rel_emb,
    const float4* __restrict__ rel_map_emb,
    float4* __restrict__ out,
    int B)
{
    int gtid = blockIdx.x * blockDim.x + threadIdx.x;
    int row  = gtid >> 5;
    int lane = gtid & 31;
    if (row >= B) return;

    unsigned long long pol;
    asm volatile("createpolicy.fractional.L2::evict_last.b64 %0, 1.0;" : "=l"(pol));

    // Index loads: broadcast within warp.
    int hi = __ldg(&head[row]);
    int ri = __ldg(&relation[row]);
    int ti = __ldg(&tail[row]);

    long hoff = (long)hi * DV4 + lane;
    long toff = (long)ti * DV4 + lane;
    long roff = (long)ri * DV4 + lane;

    // Front-batch all 6 independent loads for MLP (best-profiled config).
    float4 hv = ldg_evl(&ent_emb[hoff], pol);
    float4 hp = ldg_evl(&ent_map_emb[hoff], pol);
    float4 tv = ldg_evl(&ent_emb[toff], pol);
    float4 tp = ldg_evl(&ent_map_emb[toff], pol);
    float4 rv = __ldg(&rel_emb[roff]);
    float4 rp = __ldg(&rel_map_emb[roff]);

    // Per-lane partial dot products; combine before reduction.
    float sh = hv.x * hp.x + hv.y * hp.y + hv.z * hp.z + hv.w * hp.w;
    float st = tv.x * tp.x + tv.y * tp.y + tv.z * tp.z + tv.w * tp.w;
    float s = sh - st;

    // Warp butterfly reduction.
    #pragma unroll
    for (int o = 16; o > 0; o >>= 1) {
        s += __shfl_xor_sync(0xffffffffu, s, o);
    }

    float4 o4;
    o4.x = hv.x - tv.x + rv.x + rp.x * s;
    o4.y = hv.y - tv.y + rv.y + rp.y * s;
    o4.z = hv.z - tv.z + rv.z + rp.z * s;
    o4.w = hv.w - tv.w + rv.w + rp.w * s;

    // Write-through store: don't allocate L2 for the 128MB output stream.
    __stwt(&out[(long)row * DV4 + lane], o4);
}

extern "C" void kernel_launch(void* const* d_in, const int* in_sizes, int n_in,
                              void* d_out, int out_size)
{
    const int*    head    = (const int*)d_in[0];
    const int*    rel     = (const int*)d_in[1];
    const int*    tail    = (const int*)d_in[2];
    const float4* ent     = (const float4*)d_in[3];
    const float4* ent_map = (const float4*)d_in[4];
    const float4* rel_e   = (const float4*)d_in[5];
    const float4* rel_map = (const float4*)d_in[6];
    float4*       out     = (float4*)d_out;

    int B = in_sizes[0];
    int blocks = (B + 7) / 8;   // 8 warps (rows) per 256-thread block
    transd_kernel<<<blocks, 256>>>(head, rel, tail, ent, ent_map, rel_e, rel_map, out, B);
}

// round 8
// speedup vs baseline: 1.2294x; 1.0013x over previous
#include <cuda_runtime.h>

// TransD scoring: out = h - t + r + rp * ((hp.h) - (tp.t))
// One warp per row; lane i handles one float4 (D=128, D/4=32 == warp width).
// Roofline-bound: ~643MB irreducible traffic @ ~6.5TB/s effective (measured
// chip ceiling). All L2-policy levers tested R4-R7; kept the best-profiled
// combination: evict_last entity gathers + write-through output stores.
// This round: 512-thread blocks (halve CTA count, less scheduling overhead).

static constexpr int DV4 = 32;  // 128 floats / 4

__device__ __forceinline__ float4 ldg_evl(const float4* p, unsigned long long pol) {
    float4 v;
    asm volatile("ld.global.nc.L2::cache_hint.v4.f32 {%0,%1,%2,%3}, [%4], %5;"
                 : "=f"(v.x), "=f"(v.y), "=f"(v.z), "=f"(v.w)
                 : "l"(p), "l"(pol));
    return v;
}

__global__ __launch_bounds__(512) void transd_kernel(
    const int* __restrict__ head,
    const int* __restrict__ relation,
    const int* __restrict__ tail,
    const float4* __restrict__ ent_emb,
    const float4* __restrict__ ent_map_emb,
    const float4* __restrict__ rel_emb,
    const float4* __restrict__ rel_map_emb,
    float4* __restrict__ out,
    int B)
{
    int gtid = blockIdx.x * blockDim.x + threadIdx.x;
    int row  = gtid >> 5;
    int lane = gtid & 31;
    if (row >= B) return;

    unsigned long long pol;
    asm volatile("createpolicy.fractional.L2::evict_last.b64 %0, 1.0;" : "=l"(pol));

    // Index loads: broadcast within warp.
    int hi = __ldg(&head[row]);
    int ri = __ldg(&relation[row]);
    int ti = __ldg(&tail[row]);

    long hoff = (long)hi * DV4 + lane;
    long toff = (long)ti * DV4 + lane;
    long roff = (long)ri * DV4 + lane;

    // Front-batch all 6 independent loads for MLP.
    float4 hv = ldg_evl(&ent_emb[hoff], pol);
    float4 hp = ldg_evl(&ent_map_emb[hoff], pol);
    float4 tv = ldg_evl(&ent_emb[toff], pol);
    float4 tp = ldg_evl(&ent_map_emb[toff], pol);
    float4 rv = __ldg(&rel_emb[roff]);
    float4 rp = __ldg(&rel_map_emb[roff]);

    // Per-lane partial dot products; combine before reduction.
    float sh = hv.x * hp.x + hv.y * hp.y + hv.z * hp.z + hv.w * hp.w;
    float st = tv.x * tp.x + tv.y * tp.y + tv.z * tp.z + tv.w * tp.w;
    float s = sh - st;

    // Warp butterfly reduction.
    #pragma unroll
    for (int o = 16; o > 0; o >>= 1) {
        s += __shfl_xor_sync(0xffffffffu, s, o);
    }

    float4 o4;
    o4.x = hv.x - tv.x + rv.x + rp.x * s;
    o4.y = hv.y - tv.y + rv.y + rp.y * s;
    o4.z = hv.z - tv.z + rv.z + rp.z * s;
    o4.w = hv.w - tv.w + rv.w + rp.w * s;

    // Write-through store: don't allocate L2 for the 128MB output stream.
    __stwt(&out[(long)row * DV4 + lane], o4);
}

extern "C" void kernel_launch(void* const* d_in, const int* in_sizes, int n_in,
                              void* d_out, int out_size)
{
    const int*    head    = (const int*)d_in[0];
    const int*    rel     = (const int*)d_in[1];
    const int*    tail    = (const int*)d_in[2];
    const float4* ent     = (const float4*)d_in[3];
    const float4* ent_map = (const float4*)d_in[4];
    const float4* rel_e   = (const float4*)d_in[5];
    const float4* rel_map = (const float4*)d_in[6];
    float4*       out     = (float4*)d_out;

    int B = in_sizes[0];
    int blocks = (B + 15) / 16;   // 16 warps (rows) per 512-thread block
    transd_kernel<<<blocks, 512>>>(head, rel, tail, ent, ent_map, rel_e, rel_map, out, B);
}